// round 1
// baseline (speedup 1.0000x reference)
#include <cuda_runtime.h>
#include <math.h>

#define BATCH 2
#define SEQ   2048
#define EMB   1024
#define NH    16
#define DH    64
#define M_TOT (BATCH*SEQ)   // 4096

// Head-major scratch [B,H,S,D], fp32, 16MB each.
__device__ float g_Q[BATCH*NH*SEQ*DH];
__device__ float g_K[BATCH*NH*SEQ*DH];
__device__ float g_V[BATCH*NH*SEQ*DH];
__device__ float g_O[BATCH*NH*SEQ*DH];

// ---------------------------------------------------------------------------
// SGEMM: C[M,N] = A[M,K] * B[K,N], M=4096, N=1024, K=1024.
// Tiles: BM=128, BN=128, BK=8. 256 threads, 8x8 per thread.
// MODE 0: A = x (plain), B selected by blockIdx.z (Wq/Wk/Wv), C scattered to
//         head-major g_Q/g_K/g_V.
// MODE 1: A gathered from head-major g_O, B = B0 (Wo), C plain to Cout.
// ---------------------------------------------------------------------------
template<int MODE>
__global__ __launch_bounds__(256, 2)
void sgemm_kernel(const float* __restrict__ A,
                  const float* __restrict__ B0,
                  const float* __restrict__ B1,
                  const float* __restrict__ B2,
                  float* __restrict__ Cout)
{
    const int M = M_TOT, N = EMB, K = EMB;
    __shared__ float As[8][128];
    __shared__ float Bs[8][128];

    const int bx = blockIdx.x;       // N tile
    const int by = blockIdx.y;       // M tile
    const int tid = threadIdx.x;

    const float* B = B0;
    if (MODE == 0) {
        B = (blockIdx.z == 0) ? B0 : (blockIdx.z == 1 ? B1 : B2);
    }

    const int trow = tid / 16;       // 0..15
    const int tcol = tid % 16;       // 0..15

    // A tile load: each thread one float4. 128 rows x 8 cols.
    const int aRow  = tid >> 1;          // 0..127
    const int aCol4 = (tid & 1) << 2;    // 0 or 4
    // B tile load: 8 rows x 128 cols.
    const int bRow  = tid >> 5;          // 0..7
    const int bCol4 = (tid & 31) << 2;   // 0..124

    float acc[8][8];
#pragma unroll
    for (int i = 0; i < 8; i++)
#pragma unroll
        for (int j = 0; j < 8; j++) acc[i][j] = 0.0f;

    for (int k0 = 0; k0 < K; k0 += 8) {
        float4 av;
        if (MODE == 0) {
            av = *(const float4*)&A[(size_t)(by*128 + aRow)*K + k0 + aCol4];
        } else {
            // gather from g_O head-major: m=(b,s), k=(h,d)
            int m = by*128 + aRow;
            int b = m >> 11;           // /2048
            int s = m & 2047;
            int kk = k0 + aCol4;
            int h = kk >> 6;
            int d = kk & 63;
            av = *(const float4*)&g_O[(((size_t)(b*NH + h))*SEQ + s)*DH + d];
        }
        As[aCol4+0][aRow] = av.x;
        As[aCol4+1][aRow] = av.y;
        As[aCol4+2][aRow] = av.z;
        As[aCol4+3][aRow] = av.w;

        float4 bv = *(const float4*)&B[(size_t)(k0 + bRow)*N + bx*128 + bCol4];
        *(float4*)&Bs[bRow][bCol4] = bv;

        __syncthreads();

#pragma unroll
        for (int kk = 0; kk < 8; kk++) {
            float4 a0 = *(const float4*)&As[kk][trow*8];
            float4 a1 = *(const float4*)&As[kk][trow*8 + 4];
            float4 b0 = *(const float4*)&Bs[kk][tcol*8];
            float4 b1 = *(const float4*)&Bs[kk][tcol*8 + 4];
            float ar[8] = {a0.x,a0.y,a0.z,a0.w,a1.x,a1.y,a1.z,a1.w};
            float br[8] = {b0.x,b0.y,b0.z,b0.w,b1.x,b1.y,b1.z,b1.w};
#pragma unroll
            for (int i = 0; i < 8; i++)
#pragma unroll
                for (int j = 0; j < 8; j++)
                    acc[i][j] += ar[i]*br[j];
        }
        __syncthreads();
    }

    // Epilogue
#pragma unroll
    for (int i = 0; i < 8; i++) {
        int m = by*128 + trow*8 + i;
#pragma unroll
        for (int j = 0; j < 8; j += 4) {
            int n = bx*128 + tcol*8 + j;
            float4 v = make_float4(acc[i][j], acc[i][j+1], acc[i][j+2], acc[i][j+3]);
            if (MODE == 0) {
                int b = m >> 11;
                int s = m & 2047;
                int h = n >> 6;
                int d = n & 63;
                float* dst = (blockIdx.z == 0) ? g_Q : (blockIdx.z == 1 ? g_K : g_V);
                *(float4*)&dst[(((size_t)(b*NH + h))*SEQ + s)*DH + d] = v;
            } else {
                *(float4*)&Cout[(size_t)m*N + n] = v;
            }
        }
    }
}

// ---------------------------------------------------------------------------
// Flash attention (fp32, causal). One CTA per (q-tile of 64, head, batch).
// 256 threads = 8 warps, each warp owns 8 q-rows; lane owns k-cols
// {lane, lane+32} for scores and d-cols {lane, lane+32} for output.
// ---------------------------------------------------------------------------
#define LDSK 68                       // padded row stride for Q/K/V tiles
#define FLASH_SMEM ((3*64*LDSK + 64*64) * 4)   // 68608 bytes

__global__ __launch_bounds__(256)
void flash_attn_kernel()
{
    const int qt = blockIdx.x;        // 0..31
    const int h  = blockIdx.y;
    const int b  = blockIdx.z;

    const size_t head_off = ((size_t)(b*NH + h))*SEQ*DH;
    const float* Qp = g_Q + head_off;
    const float* Kp = g_K + head_off;
    const float* Vp = g_V + head_off;
    float*       Op = g_O + head_off;

    extern __shared__ float sm[];
    float* Qs = sm;                   // 64 x 68
    float* Ks = Qs + 64*LDSK;         // 64 x 68
    float* Vs = Ks + 64*LDSK;         // 64 x 68
    float* Ps = Vs + 64*LDSK;         // 64 x 64 (per-warp rows)

    const int tid  = threadIdx.x;
    const int w    = tid >> 5;        // warp 0..7
    const int lane = tid & 31;

    const float scale = 0.125f;       // 1/sqrt(64)

    // Load Q tile (64 x 64) cooperatively.
#pragma unroll
    for (int i = 0; i < 4; i++) {
        int lin = tid + 256*i;        // 0..1023 float4 slots
        int r  = lin >> 4;
        int c4 = (lin & 15) << 2;
        *(float4*)&Qs[r*LDSK + c4] = *(const float4*)&Qp[(size_t)(qt*64 + r)*DH + c4];
    }

    float m_i[8], l_i[8], o0[8], o1[8];
#pragma unroll
    for (int r = 0; r < 8; r++) {
        m_i[r] = -INFINITY; l_i[r] = 0.0f; o0[r] = 0.0f; o1[r] = 0.0f;
    }

    for (int j = 0; j <= qt; j++) {
        __syncthreads();
        // Load K and V tiles for k-rows [j*64, j*64+64).
#pragma unroll
        for (int i = 0; i < 4; i++) {
            int lin = tid + 256*i;
            int r  = lin >> 4;
            int c4 = (lin & 15) << 2;
            *(float4*)&Ks[r*LDSK + c4] = *(const float4*)&Kp[(size_t)(j*64 + r)*DH + c4];
            *(float4*)&Vs[r*LDSK + c4] = *(const float4*)&Vp[(size_t)(j*64 + r)*DH + c4];
        }
        __syncthreads();

        // --- scores: s[r][{0,1}] = Q[8w+r,:] . K[{lane,lane+32},:] ---
        float s0[8], s1[8];
#pragma unroll
        for (int r = 0; r < 8; r++) { s0[r] = 0.0f; s1[r] = 0.0f; }

#pragma unroll
        for (int d4 = 0; d4 < 16; d4++) {
            float4 k0 = *(const float4*)&Ks[lane*LDSK + d4*4];
            float4 k1 = *(const float4*)&Ks[(lane+32)*LDSK + d4*4];
#pragma unroll
            for (int r = 0; r < 8; r++) {
                float4 q = *(const float4*)&Qs[(8*w + r)*LDSK + d4*4];
                s0[r] += q.x*k0.x + q.y*k0.y + q.z*k0.z + q.w*k0.w;
                s1[r] += q.x*k1.x + q.y*k1.y + q.z*k1.z + q.w*k1.w;
            }
        }

        const bool diag = (j == qt);
        const int kc0 = j*64 + lane;
        const int kc1 = kc0 + 32;

        // --- online softmax per row ---
#pragma unroll
        for (int r = 0; r < 8; r++) {
            float sc0 = s0[r]*scale;
            float sc1 = s1[r]*scale;
            if (diag) {
                int qr = qt*64 + 8*w + r;
                if (kc0 > qr) sc0 = -1e30f;
                if (kc1 > qr) sc1 = -1e30f;
            }
            float mt = fmaxf(sc0, sc1);
#pragma unroll
            for (int off = 16; off; off >>= 1)
                mt = fmaxf(mt, __shfl_xor_sync(0xffffffffu, mt, off));
            float m_new = fmaxf(m_i[r], mt);
            float corr  = __expf(m_i[r] - m_new);
            float p0 = __expf(sc0 - m_new);
            float p1 = __expf(sc1 - m_new);
            float rs = p0 + p1;
#pragma unroll
            for (int off = 16; off; off >>= 1)
                rs += __shfl_xor_sync(0xffffffffu, rs, off);
            l_i[r] = l_i[r]*corr + rs;
            m_i[r] = m_new;
            o0[r] *= corr;
            o1[r] *= corr;
            Ps[(8*w + r)*64 + lane]      = p0;
            Ps[(8*w + r)*64 + lane + 32] = p1;
        }
        __syncwarp();

        // --- PV: o[r][{lane,lane+32}] += P[r,:] . V[:, d] ---
#pragma unroll
        for (int c4 = 0; c4 < 16; c4++) {
            float v0[4], v1[4];
#pragma unroll
            for (int i = 0; i < 4; i++) {
                v0[i] = Vs[(c4*4 + i)*LDSK + lane];
                v1[i] = Vs[(c4*4 + i)*LDSK + lane + 32];
            }
#pragma unroll
            for (int r = 0; r < 8; r++) {
                float4 p = *(const float4*)&Ps[(8*w + r)*64 + c4*4];
                o0[r] += p.x*v0[0] + p.y*v0[1] + p.z*v0[2] + p.w*v0[3];
                o1[r] += p.x*v1[0] + p.y*v1[1] + p.z*v1[2] + p.w*v1[3];
            }
        }
    }

    // Normalize and write O (head-major).
#pragma unroll
    for (int r = 0; r < 8; r++) {
        float inv = 1.0f / l_i[r];
        int row = qt*64 + 8*w + r;
        Op[(size_t)row*DH + lane]      = o0[r]*inv;
        Op[(size_t)row*DH + lane + 32] = o1[r]*inv;
    }
}

// ---------------------------------------------------------------------------
extern "C" void kernel_launch(void* const* d_in, const int* in_sizes, int n_in,
                              void* d_out, int out_size)
{
    const float* x  = (const float*)d_in[0];
    const float* Wq = (const float*)d_in[1];
    const float* Wk = (const float*)d_in[2];
    const float* Wv = (const float*)d_in[3];
    const float* Wo = (const float*)d_in[4];
    float* out = (float*)d_out;

    cudaFuncSetAttribute(flash_attn_kernel,
                         cudaFuncAttributeMaxDynamicSharedMemorySize, FLASH_SMEM);

    // QKV projections with head-major scatter.
    sgemm_kernel<0><<<dim3(EMB/128, M_TOT/128, 3), 256>>>(x, Wq, Wk, Wv, nullptr);

    // Causal flash attention.
    flash_attn_kernel<<<dim3(SEQ/64, NH, BATCH), 256, FLASH_SMEM>>>();

    // Output projection (gathers head-major O).
    sgemm_kernel<1><<<dim3(EMB/128, M_TOT/128, 1), 256>>>(nullptr, Wo, nullptr, nullptr, out);
}

// round 3
// speedup vs baseline: 1.4448x; 1.4448x over previous
#include <cuda_runtime.h>
#include <cuda_bf16.h>
#include <math.h>
#include <stdint.h>

#define BATCH 2
#define SEQ   2048
#define EMB   1024
#define NH    16
#define DH    64
#define M_TOT (BATCH*SEQ)   // 4096

// ---------------------------------------------------------------------------
// Device scratch
// ---------------------------------------------------------------------------
__device__ float g_Q[BATCH*NH*SEQ*DH];
__device__ float g_K[BATCH*NH*SEQ*DH];
__device__ float g_V[BATCH*NH*SEQ*DH];
__device__ float g_O[BATCH*NH*SEQ*DH];

// bf16 hi/lo operands, row-major.
// X/O: [M_TOT][EMB].  W^T: [4][EMB(n)][EMB(k)].
__device__ __nv_bfloat16 g_Xhi[M_TOT*EMB];
__device__ __nv_bfloat16 g_Xlo[M_TOT*EMB];
__device__ __nv_bfloat16 g_Whi[4*EMB*EMB];
__device__ __nv_bfloat16 g_Wlo[4*EMB*EMB];
__device__ __nv_bfloat16 g_Ohi[M_TOT*EMB];
__device__ __nv_bfloat16 g_Olo[M_TOT*EMB];

// ---------------------------------------------------------------------------
// PTX helpers (portable: sm_80-class features only)
// ---------------------------------------------------------------------------
__device__ __forceinline__ uint32_t smem_u32(const void* p) {
    uint32_t a;
    asm("{ .reg .u64 t; cvta.to.shared.u64 t, %1; cvt.u32.u64 %0, t; }" : "=r"(a) : "l"(p));
    return a;
}

#define CP_ASYNC16(dst, src) \
    asm volatile("cp.async.cg.shared.global [%0], [%1], 16;" :: "r"(dst), "l"(src))
#define CP_COMMIT() asm volatile("cp.async.commit_group;")
#define CP_WAIT1()  asm volatile("cp.async.wait_group 1;")

#define LDSM4(r, addr) \
    asm volatile("ldmatrix.sync.aligned.m8n8.x4.shared.b16 {%0,%1,%2,%3}, [%4];" \
        : "=r"((r)[0]), "=r"((r)[1]), "=r"((r)[2]), "=r"((r)[3]) : "r"(addr))

#define MMA_BF16(c, a, b0v, b1v) \
    asm volatile("mma.sync.aligned.m16n8k16.row.col.f32.bf16.bf16.f32 " \
        "{%0,%1,%2,%3}, {%4,%5,%6,%7}, {%8,%9}, {%0,%1,%2,%3};" \
        : "+f"((c)[0]), "+f"((c)[1]), "+f"((c)[2]), "+f"((c)[3]) \
        : "r"((a)[0]), "r"((a)[1]), "r"((a)[2]), "r"((a)[3]), "r"(b0v), "r"(b1v))

// ---------------------------------------------------------------------------
// Conversion kernels: fp32 -> bf16 hi/lo (row-major)
// ---------------------------------------------------------------------------
__device__ __forceinline__ void split8_store(const float* vs, __nv_bfloat16* hi,
                                             __nv_bfloat16* lo, size_t base) {
    __nv_bfloat16 h[8], l[8];
#pragma unroll
    for (int i = 0; i < 8; i++) {
        h[i] = __float2bfloat16(vs[i]);
        l[i] = __float2bfloat16(vs[i] - __bfloat162float(h[i]));
    }
    *(uint4*)&hi[base] = *(uint4*)h;
    *(uint4*)&lo[base] = *(uint4*)l;
}

__global__ void convert_x_kernel(const float* __restrict__ X) {
    int gid = blockIdx.x * 256 + threadIdx.x;
    size_t base = (size_t)gid * 8;
    float4 v0 = *(const float4*)&X[base];
    float4 v1 = *(const float4*)&X[base + 4];
    float vs[8] = {v0.x, v0.y, v0.z, v0.w, v1.x, v1.y, v1.z, v1.w};
    split8_store(vs, g_Xhi, g_Xlo, base);
}

__global__ void convert_o_kernel() {
    int gid = blockIdx.x * 256 + threadIdx.x;
    int m = gid >> 7;
    int k = (gid & 127) << 3;
    int b = m >> 11, s = m & 2047, h = k >> 6, d = k & 63;
    const float* src = &g_O[(((size_t)(b * NH + h)) * SEQ + s) * DH + d];
    float4 v0 = *(const float4*)&src[0];
    float4 v1 = *(const float4*)&src[4];
    float vs[8] = {v0.x, v0.y, v0.z, v0.w, v1.x, v1.y, v1.z, v1.w};
    split8_store(vs, g_Ohi, g_Olo, (size_t)m * EMB + k);
}

// Transpose W[K][N] -> Wt[N][K] while converting to hi/lo.
__global__ void convert_w_kernel(const float* __restrict__ W0, const float* __restrict__ W1,
                                 const float* __restrict__ W2, const float* __restrict__ W3) {
    __shared__ float Wsm[64][129];
    int bi = blockIdx.x;                 // 0..511
    int w = bi >> 7;
    int rest = bi & 127;
    int ntile = rest >> 4;               // 0..7 (128 n each)
    int kc = rest & 15;                  // 0..15 (64 k each)
    const float* W = (w == 0) ? W0 : (w == 1) ? W1 : (w == 2) ? W2 : W3;
    int tid = threadIdx.x;

#pragma unroll
    for (int i = 0; i < 32; i++) {
        int lin = i * 256 + tid;
        int kr = lin >> 7;
        int nc = lin & 127;
        Wsm[kr][nc] = W[(size_t)(kc * 64 + kr) * EMB + ntile * 128 + nc];
    }
    __syncthreads();

#pragma unroll
    for (int j = 0; j < 4; j++) {
        int lin = j * 256 + tid;
        int nin = lin >> 3;              // 0..127
        int g = lin & 7;                 // k-group of 8
        float vs[8];
#pragma unroll
        for (int i = 0; i < 8; i++) vs[i] = Wsm[g * 8 + i][nin];
        size_t base = ((size_t)(w * EMB + ntile * 128 + nin)) * EMB + kc * 64 + g * 8;
        split8_store(vs, g_Whi, g_Wlo, base);
    }
}

// ---------------------------------------------------------------------------
// mma.sync bf16x3 GEMM: C = A*W (fp32 acc). CTA tile 128x128, BK=32, 3 stages.
// Warp layout 4(m) x 2(n); warp tile 32x64.
// MODE 0: A=X, B=W[blockIdx.z], scatter C head-major to g_Q/g_K/g_V.
// MODE 1: A=O(row-major converted), B=W[3], C row-major to Cout.
// ---------------------------------------------------------------------------
#define TILE_BYTES 10240                 // 128 rows * 80B (32 bf16 + pad)
#define STAGE_BYTES (4*TILE_BYTES)       // Ah, Al, Bh, Bl
#define GEMM_SMEM (3*STAGE_BYTES)        // 122880

template<int MODE>
__global__ __launch_bounds__(256)
void gemm_mma(const __nv_bfloat16* __restrict__ Ahi,
              const __nv_bfloat16* __restrict__ Alo,
              float* __restrict__ Cout)
{
    extern __shared__ __align__(128) char smem[];
    const uint32_t sb = smem_u32(smem);
    const int tid = threadIdx.x, lane = tid & 31, wid = tid >> 5;
    const int wm = wid & 3, wn = wid >> 2;
    const int bx = blockIdx.x, by = blockIdx.y;
    const int w = (MODE == 0) ? blockIdx.z : 3;

    const __nv_bfloat16* Bhi = g_Whi + (size_t)w * EMB * EMB;
    const __nv_bfloat16* Blo = g_Wlo + (size_t)w * EMB * EMB;

    float acc[2][8][4];
#pragma unroll
    for (int i = 0; i < 2; i++)
#pragma unroll
        for (int j = 0; j < 8; j++)
#pragma unroll
            for (int q = 0; q < 4; q++) acc[i][j][q] = 0.0f;

    // Per-thread load coords (8 cp.async of 16B each per stage)
    const int lr = tid >> 2;             // row within 64-row half
    const int ls4 = tid & 3;             // 16B segment within 64B row

    auto load_stage = [&](int c, int slot) {
        const int k0 = c * 32;
        const uint32_t st = sb + slot * STAGE_BYTES;
#pragma unroll
        for (int i = 0; i < 8; i++) {
            const int t = i >> 1;
            const int r = (i & 1) * 64 + lr;
            const __nv_bfloat16* g;
            if (t == 0)      g = Ahi + (size_t)(by * 128 + r) * EMB + k0 + ls4 * 8;
            else if (t == 1) g = Alo + (size_t)(by * 128 + r) * EMB + k0 + ls4 * 8;
            else if (t == 2) g = Bhi + (size_t)(bx * 128 + r) * EMB + k0 + ls4 * 8;
            else             g = Blo + (size_t)(bx * 128 + r) * EMB + k0 + ls4 * 8;
            const uint32_t dst = st + t * TILE_BYTES + r * 80 + ls4 * 16;
            CP_ASYNC16(dst, g);
        }
        CP_COMMIT();
    };

    load_stage(0, 0);
    load_stage(1, 1);

    // ldmatrix address components
    const uint32_t aRowB  = (wm * 32 + (lane & 15)) * 80;
    const uint32_t aColB  = (lane >> 4) * 16;                       // bytes
    const uint32_t bRowB  = (wn * 64 + (lane & 7) + ((lane >> 4) << 3)) * 80;
    const uint32_t bColB  = ((lane >> 3) & 1) * 16;                 // bytes

    for (int c = 0; c < 32; c++) {
        CP_WAIT1();
        __syncthreads();
        const uint32_t st = sb + (c % 3) * STAGE_BYTES;
        const uint32_t atH = st, atL = st + TILE_BYTES;
        const uint32_t btH = st + 2 * TILE_BYTES, btL = st + 3 * TILE_BYTES;

#pragma unroll
        for (int kc = 0; kc < 2; kc++) {
            const uint32_t kB = kc * 32;   // k16 step = 16 bf16 = 32B
            uint32_t ah[2][4], al[2][4], bb[4][4];

            // Ah, Bh
#pragma unroll
            for (int mi = 0; mi < 2; mi++)
                LDSM4(ah[mi], atH + aRowB + mi * (16 * 80) + kB + aColB);
#pragma unroll
            for (int ni = 0; ni < 4; ni++)
                LDSM4(bb[ni], btH + bRowB + ni * (16 * 80) + kB + bColB);

            // hh
#pragma unroll
            for (int mi = 0; mi < 2; mi++)
#pragma unroll
                for (int ni = 0; ni < 4; ni++) {
                    MMA_BF16(acc[mi][2 * ni],     ah[mi], bb[ni][0], bb[ni][1]);
                    MMA_BF16(acc[mi][2 * ni + 1], ah[mi], bb[ni][2], bb[ni][3]);
                }

            // Al; lh = Al*Bh
#pragma unroll
            for (int mi = 0; mi < 2; mi++)
                LDSM4(al[mi], atL + aRowB + mi * (16 * 80) + kB + aColB);
#pragma unroll
            for (int mi = 0; mi < 2; mi++)
#pragma unroll
                for (int ni = 0; ni < 4; ni++) {
                    MMA_BF16(acc[mi][2 * ni],     al[mi], bb[ni][0], bb[ni][1]);
                    MMA_BF16(acc[mi][2 * ni + 1], al[mi], bb[ni][2], bb[ni][3]);
                }

            // Bl (reuse bb regs); hl = Ah*Bl
#pragma unroll
            for (int ni = 0; ni < 4; ni++)
                LDSM4(bb[ni], btL + bRowB + ni * (16 * 80) + kB + bColB);
#pragma unroll
            for (int mi = 0; mi < 2; mi++)
#pragma unroll
                for (int ni = 0; ni < 4; ni++) {
                    MMA_BF16(acc[mi][2 * ni],     ah[mi], bb[ni][0], bb[ni][1]);
                    MMA_BF16(acc[mi][2 * ni + 1], ah[mi], bb[ni][2], bb[ni][3]);
                }
        }
        __syncthreads();
        if (c + 2 < 32) load_stage(c + 2, (c + 2) % 3);
    }

    // Epilogue: accum -> smem (reuse pipeline smem), then coalesced scatter.
    float* Cs = (float*)smem;            // [128][132]
#pragma unroll
    for (int mi = 0; mi < 2; mi++)
#pragma unroll
        for (int nf = 0; nf < 8; nf++) {
            const int row0 = wm * 32 + mi * 16 + (lane >> 2);
            const int col  = wn * 64 + nf * 8 + (lane & 3) * 2;
            *(float2*)&Cs[row0 * 132 + col]       = make_float2(acc[mi][nf][0], acc[mi][nf][1]);
            *(float2*)&Cs[(row0 + 8) * 132 + col] = make_float2(acc[mi][nf][2], acc[mi][nf][3]);
        }
    __syncthreads();

#pragma unroll
    for (int it = 0; it < 16; it++) {
        const int lin = it * 256 + tid;  // 4096 float4 slots
        const int rr = lin >> 5;
        const int cg = (lin & 31) * 4;
        float4 v = *(const float4*)&Cs[rr * 132 + cg];
        const int m = by * 128 + rr;
        const int n = bx * 128 + cg;
        if (MODE == 0) {
            const int b = m >> 11, s = m & 2047, h = n >> 6, d = n & 63;
            float* dst = (blockIdx.z == 0) ? g_Q : (blockIdx.z == 1 ? g_K : g_V);
            *(float4*)&dst[(((size_t)(b * NH + h)) * SEQ + s) * DH + d] = v;
        } else {
            *(float4*)&Cout[(size_t)m * EMB + n] = v;
        }
    }
}

// ---------------------------------------------------------------------------
// Flash attention (fp32, causal) — unchanged (known correct).
// ---------------------------------------------------------------------------
#define LDSK 68
#define FLASH_SMEM ((3*64*LDSK + 64*64) * 4)

__global__ __launch_bounds__(256)
void flash_attn_kernel()
{
    const int qt = blockIdx.x;
    const int h  = blockIdx.y;
    const int b  = blockIdx.z;

    const size_t head_off = ((size_t)(b*NH + h))*SEQ*DH;
    const float* Qp = g_Q + head_off;
    const float* Kp = g_K + head_off;
    const float* Vp = g_V + head_off;
    float*       Op = g_O + head_off;

    extern __shared__ float sm[];
    float* Qs = sm;
    float* Ks = Qs + 64*LDSK;
    float* Vs = Ks + 64*LDSK;
    float* Ps = Vs + 64*LDSK;

    const int tid  = threadIdx.x;
    const int w    = tid >> 5;
    const int lane = tid & 31;
    const float scale = 0.125f;

#pragma unroll
    for (int i = 0; i < 4; i++) {
        int lin = tid + 256*i;
        int r  = lin >> 4;
        int c4 = (lin & 15) << 2;
        *(float4*)&Qs[r*LDSK + c4] = *(const float4*)&Qp[(size_t)(qt*64 + r)*DH + c4];
    }

    float m_i[8], l_i[8], o0[8], o1[8];
#pragma unroll
    for (int r = 0; r < 8; r++) {
        m_i[r] = -INFINITY; l_i[r] = 0.0f; o0[r] = 0.0f; o1[r] = 0.0f;
    }

    for (int j = 0; j <= qt; j++) {
        __syncthreads();
#pragma unroll
        for (int i = 0; i < 4; i++) {
            int lin = tid + 256*i;
            int r  = lin >> 4;
            int c4 = (lin & 15) << 2;
            *(float4*)&Ks[r*LDSK + c4] = *(const float4*)&Kp[(size_t)(j*64 + r)*DH + c4];
            *(float4*)&Vs[r*LDSK + c4] = *(const float4*)&Vp[(size_t)(j*64 + r)*DH + c4];
        }
        __syncthreads();

        float s0[8], s1[8];
#pragma unroll
        for (int r = 0; r < 8; r++) { s0[r] = 0.0f; s1[r] = 0.0f; }

#pragma unroll
        for (int d4 = 0; d4 < 16; d4++) {
            float4 k0 = *(const float4*)&Ks[lane*LDSK + d4*4];
            float4 k1 = *(const float4*)&Ks[(lane+32)*LDSK + d4*4];
#pragma unroll
            for (int r = 0; r < 8; r++) {
                float4 q = *(const float4*)&Qs[(8*w + r)*LDSK + d4*4];
                s0[r] += q.x*k0.x + q.y*k0.y + q.z*k0.z + q.w*k0.w;
                s1[r] += q.x*k1.x + q.y*k1.y + q.z*k1.z + q.w*k1.w;
            }
        }

        const bool diag = (j == qt);
        const int kc0 = j*64 + lane;
        const int kc1 = kc0 + 32;

#pragma unroll
        for (int r = 0; r < 8; r++) {
            float sc0 = s0[r]*scale;
            float sc1 = s1[r]*scale;
            if (diag) {
                int qr = qt*64 + 8*w + r;
                if (kc0 > qr) sc0 = -1e30f;
                if (kc1 > qr) sc1 = -1e30f;
            }
            float mt = fmaxf(sc0, sc1);
#pragma unroll
            for (int off = 16; off; off >>= 1)
                mt = fmaxf(mt, __shfl_xor_sync(0xffffffffu, mt, off));
            float m_new = fmaxf(m_i[r], mt);
            float corr  = __expf(m_i[r] - m_new);
            float p0 = __expf(sc0 - m_new);
            float p1 = __expf(sc1 - m_new);
            float rs = p0 + p1;
#pragma unroll
            for (int off = 16; off; off >>= 1)
                rs += __shfl_xor_sync(0xffffffffu, rs, off);
            l_i[r] = l_i[r]*corr + rs;
            m_i[r] = m_new;
            o0[r] *= corr;
            o1[r] *= corr;
            Ps[(8*w + r)*64 + lane]      = p0;
            Ps[(8*w + r)*64 + lane + 32] = p1;
        }
        __syncwarp();

#pragma unroll
        for (int c4 = 0; c4 < 16; c4++) {
            float v0[4], v1[4];
#pragma unroll
            for (int i = 0; i < 4; i++) {
                v0[i] = Vs[(c4*4 + i)*LDSK + lane];
                v1[i] = Vs[(c4*4 + i)*LDSK + lane + 32];
            }
#pragma unroll
            for (int r = 0; r < 8; r++) {
                float4 p = *(const float4*)&Ps[(8*w + r)*64 + c4*4];
                o0[r] += p.x*v0[0] + p.y*v0[1] + p.z*v0[2] + p.w*v0[3];
                o1[r] += p.x*v1[0] + p.y*v1[1] + p.z*v1[2] + p.w*v1[3];
            }
        }
    }

#pragma unroll
    for (int r = 0; r < 8; r++) {
        float inv = 1.0f / l_i[r];
        int row = qt*64 + 8*w + r;
        Op[(size_t)row*DH + lane]      = o0[r]*inv;
        Op[(size_t)row*DH + lane + 32] = o1[r]*inv;
    }
}

// ---------------------------------------------------------------------------
extern "C" void kernel_launch(void* const* d_in, const int* in_sizes, int n_in,
                              void* d_out, int out_size)
{
    const float* x  = (const float*)d_in[0];
    const float* Wq = (const float*)d_in[1];
    const float* Wk = (const float*)d_in[2];
    const float* Wv = (const float*)d_in[3];
    const float* Wo = (const float*)d_in[4];
    float* out = (float*)d_out;

    cudaFuncSetAttribute(gemm_mma<0>,
                         cudaFuncAttributeMaxDynamicSharedMemorySize, GEMM_SMEM);
    cudaFuncSetAttribute(gemm_mma<1>,
                         cudaFuncAttributeMaxDynamicSharedMemorySize, GEMM_SMEM);
    cudaFuncSetAttribute(flash_attn_kernel,
                         cudaFuncAttributeMaxDynamicSharedMemorySize, FLASH_SMEM);

    __nv_bfloat16 *xhi_p, *xlo_p, *ohi_p, *olo_p;
    cudaGetSymbolAddress((void**)&xhi_p, g_Xhi);
    cudaGetSymbolAddress((void**)&xlo_p, g_Xlo);
    cudaGetSymbolAddress((void**)&ohi_p, g_Ohi);
    cudaGetSymbolAddress((void**)&olo_p, g_Olo);

    // Convert inputs to bf16 hi/lo.
    convert_x_kernel<<<2048, 256>>>(x);
    convert_w_kernel<<<512, 256>>>(Wq, Wk, Wv, Wo);

    // QKV projections on tensor cores (bf16x3), scattered head-major.
    gemm_mma<0><<<dim3(8, 32, 3), 256, GEMM_SMEM>>>(xhi_p, xlo_p, nullptr);

    // Causal flash attention (fp32).
    flash_attn_kernel<<<dim3(SEQ/64, NH, BATCH), 256, FLASH_SMEM>>>();

    // Convert O, then output projection.
    convert_o_kernel<<<2048, 256>>>();
    gemm_mma<1><<<dim3(8, 32, 1), 256, GEMM_SMEM>>>(ohi_p, olo_p, out);
}

// round 4
// speedup vs baseline: 2.8712x; 1.9872x over previous
#include <cuda_runtime.h>
#include <cuda_bf16.h>
#include <math.h>
#include <stdint.h>

#define BATCH 2
#define SEQ   2048
#define EMB   1024
#define NH    16
#define DH    64
#define M_TOT (BATCH*SEQ)   // 4096

// ---------------------------------------------------------------------------
// Device scratch (bf16 hi/lo everywhere; no fp32 intermediates)
// ---------------------------------------------------------------------------
__device__ __nv_bfloat16 g_Xhi[M_TOT*EMB];
__device__ __nv_bfloat16 g_Xlo[M_TOT*EMB];
__device__ __nv_bfloat16 g_Whi[4*EMB*EMB];
__device__ __nv_bfloat16 g_Wlo[4*EMB*EMB];
// Q/K/V head-major [B,H,S,D]
__device__ __nv_bfloat16 g_Qhi[M_TOT*EMB/16*16]; // sized M_TOT*EMB? actually B*H*S*D = 4096*1024
__device__ __nv_bfloat16 g_Qlo[BATCH*NH*SEQ*DH];
__device__ __nv_bfloat16 g_Khi[BATCH*NH*SEQ*DH];
__device__ __nv_bfloat16 g_Klo[BATCH*NH*SEQ*DH];
__device__ __nv_bfloat16 g_Vhi[BATCH*NH*SEQ*DH];
__device__ __nv_bfloat16 g_Vlo[BATCH*NH*SEQ*DH];
// attention output, row-major [M_TOT][EMB]
__device__ __nv_bfloat16 g_Ohi[M_TOT*EMB];
__device__ __nv_bfloat16 g_Olo[M_TOT*EMB];

// ---------------------------------------------------------------------------
// PTX helpers (portable sm_80-class only; target is bare sm_103)
// ---------------------------------------------------------------------------
__device__ __forceinline__ uint32_t smem_u32(const void* p) {
    uint32_t a;
    asm("{ .reg .u64 t; cvta.to.shared.u64 t, %1; cvt.u32.u64 %0, t; }" : "=r"(a) : "l"(p));
    return a;
}

#define CP_ASYNC16(dst, src) \
    asm volatile("cp.async.cg.shared.global [%0], [%1], 16;" :: "r"(dst), "l"(src))
#define CP_COMMIT() asm volatile("cp.async.commit_group;")
#define CP_WAIT0()  asm volatile("cp.async.wait_group 0;")
#define CP_WAIT1()  asm volatile("cp.async.wait_group 1;")

#define LDSM4(r, addr) \
    asm volatile("ldmatrix.sync.aligned.m8n8.x4.shared.b16 {%0,%1,%2,%3}, [%4];" \
        : "=r"((r)[0]), "=r"((r)[1]), "=r"((r)[2]), "=r"((r)[3]) : "r"(addr))
#define LDSM4T(r, addr) \
    asm volatile("ldmatrix.sync.aligned.m8n8.x4.trans.shared.b16 {%0,%1,%2,%3}, [%4];" \
        : "=r"((r)[0]), "=r"((r)[1]), "=r"((r)[2]), "=r"((r)[3]) : "r"(addr))

#define MMA_BF16(c, a, b0v, b1v) \
    asm volatile("mma.sync.aligned.m16n8k16.row.col.f32.bf16.bf16.f32 " \
        "{%0,%1,%2,%3}, {%4,%5,%6,%7}, {%8,%9}, {%0,%1,%2,%3};" \
        : "+f"((c)[0]), "+f"((c)[1]), "+f"((c)[2]), "+f"((c)[3]) \
        : "r"((a)[0]), "r"((a)[1]), "r"((a)[2]), "r"((a)[3]), "r"(b0v), "r"(b1v))

__device__ __forceinline__ uint32_t packbf2(float lo, float hi) {
    uint32_t r;
    asm("cvt.rn.bf16x2.f32 %0, %1, %2;" : "=r"(r) : "f"(hi), "f"(lo));
    return r;
}
__device__ __forceinline__ float bflo(uint32_t u) { return __uint_as_float(u << 16); }
__device__ __forceinline__ float bfhi(uint32_t u) { return __uint_as_float(u & 0xFFFF0000u); }

__device__ __forceinline__ uint32_t swz(uint32_t off) {   // SW128 for 128B rows
    return off ^ ((off >> 3) & 0x70);
}

// ---------------------------------------------------------------------------
// Conversion kernels: fp32 -> bf16 hi/lo (row-major)
// ---------------------------------------------------------------------------
__device__ __forceinline__ void split8_store(const float* vs, __nv_bfloat16* hi,
                                             __nv_bfloat16* lo, size_t base) {
    __nv_bfloat16 h[8], l[8];
#pragma unroll
    for (int i = 0; i < 8; i++) {
        h[i] = __float2bfloat16(vs[i]);
        l[i] = __float2bfloat16(vs[i] - __bfloat162float(h[i]));
    }
    *(uint4*)&hi[base] = *(uint4*)h;
    *(uint4*)&lo[base] = *(uint4*)l;
}

__global__ void convert_x_kernel(const float* __restrict__ X) {
    int gid = blockIdx.x * 256 + threadIdx.x;
    size_t base = (size_t)gid * 8;
    float4 v0 = *(const float4*)&X[base];
    float4 v1 = *(const float4*)&X[base + 4];
    float vs[8] = {v0.x, v0.y, v0.z, v0.w, v1.x, v1.y, v1.z, v1.w};
    split8_store(vs, g_Xhi, g_Xlo, base);
}

// Transpose W[K][N] -> Wt[N][K] while converting to hi/lo.
__global__ void convert_w_kernel(const float* __restrict__ W0, const float* __restrict__ W1,
                                 const float* __restrict__ W2, const float* __restrict__ W3) {
    __shared__ float Wsm[64][129];
    int bi = blockIdx.x;                 // 0..511
    int w = bi >> 7;
    int rest = bi & 127;
    int ntile = rest >> 4;
    int kc = rest & 15;
    const float* W = (w == 0) ? W0 : (w == 1) ? W1 : (w == 2) ? W2 : W3;
    int tid = threadIdx.x;

#pragma unroll
    for (int i = 0; i < 32; i++) {
        int lin = i * 256 + tid;
        int kr = lin >> 7;
        int nc = lin & 127;
        Wsm[kr][nc] = W[(size_t)(kc * 64 + kr) * EMB + ntile * 128 + nc];
    }
    __syncthreads();

#pragma unroll
    for (int j = 0; j < 4; j++) {
        int lin = j * 256 + tid;
        int nin = lin >> 3;
        int g = lin & 7;
        float vs[8];
#pragma unroll
        for (int i = 0; i < 8; i++) vs[i] = Wsm[g * 8 + i][nin];
        size_t base = ((size_t)(w * EMB + ntile * 128 + nin)) * EMB + kc * 64 + g * 8;
        split8_store(vs, g_Whi, g_Wlo, base);
    }
}

// ---------------------------------------------------------------------------
// mma.sync bf16x3 GEMM (CTA 128x128, BK=32, 3-stage cp.async).
// MODE 0: A=X, B=W[z]; epilogue -> bf16 hi/lo head-major Q/K/V.
// MODE 1: A=Ohi/Olo,  B=W[3];  epilogue -> fp32 row-major Cout.
// ---------------------------------------------------------------------------
#define TILE_BYTES 10240                 // 128 rows * 80B
#define STAGE_BYTES (4*TILE_BYTES)
#define GEMM_SMEM (3*STAGE_BYTES)        // 122880

template<int MODE>
__global__ __launch_bounds__(256)
void gemm_mma(const __nv_bfloat16* __restrict__ Ahi,
              const __nv_bfloat16* __restrict__ Alo,
              float* __restrict__ Cout)
{
    extern __shared__ __align__(128) char smem[];
    const uint32_t sb = smem_u32(smem);
    const int tid = threadIdx.x, lane = tid & 31, wid = tid >> 5;
    const int wm = wid & 3, wn = wid >> 2;
    const int bx = blockIdx.x, by = blockIdx.y;
    const int w = (MODE == 0) ? blockIdx.z : 3;

    const __nv_bfloat16* Bhi = g_Whi + (size_t)w * EMB * EMB;
    const __nv_bfloat16* Blo = g_Wlo + (size_t)w * EMB * EMB;

    float acc[2][8][4];
#pragma unroll
    for (int i = 0; i < 2; i++)
#pragma unroll
        for (int j = 0; j < 8; j++)
#pragma unroll
            for (int q = 0; q < 4; q++) acc[i][j][q] = 0.0f;

    const int lr = tid >> 2;
    const int ls4 = tid & 3;

    auto load_stage = [&](int c, int slot) {
        const int k0 = c * 32;
        const uint32_t st = sb + slot * STAGE_BYTES;
#pragma unroll
        for (int i = 0; i < 8; i++) {
            const int t = i >> 1;
            const int r = (i & 1) * 64 + lr;
            const __nv_bfloat16* g;
            if (t == 0)      g = Ahi + (size_t)(by * 128 + r) * EMB + k0 + ls4 * 8;
            else if (t == 1) g = Alo + (size_t)(by * 128 + r) * EMB + k0 + ls4 * 8;
            else if (t == 2) g = Bhi + (size_t)(bx * 128 + r) * EMB + k0 + ls4 * 8;
            else             g = Blo + (size_t)(bx * 128 + r) * EMB + k0 + ls4 * 8;
            const uint32_t dst = st + t * TILE_BYTES + r * 80 + ls4 * 16;
            CP_ASYNC16(dst, g);
        }
        CP_COMMIT();
    };

    load_stage(0, 0);
    load_stage(1, 1);

    const uint32_t aRowB  = (wm * 32 + (lane & 15)) * 80;
    const uint32_t aColB  = (lane >> 4) * 16;
    const uint32_t bRowB  = (wn * 64 + (lane & 7) + ((lane >> 4) << 3)) * 80;
    const uint32_t bColB  = ((lane >> 3) & 1) * 16;

    for (int c = 0; c < 32; c++) {
        CP_WAIT1();
        __syncthreads();
        const uint32_t st = sb + (c % 3) * STAGE_BYTES;
        const uint32_t atH = st, atL = st + TILE_BYTES;
        const uint32_t btH = st + 2 * TILE_BYTES, btL = st + 3 * TILE_BYTES;

#pragma unroll
        for (int kc = 0; kc < 2; kc++) {
            const uint32_t kB = kc * 32;
            uint32_t ah[2][4], al[2][4], bb[4][4];
#pragma unroll
            for (int mi = 0; mi < 2; mi++)
                LDSM4(ah[mi], atH + aRowB + mi * (16 * 80) + kB + aColB);
#pragma unroll
            for (int ni = 0; ni < 4; ni++)
                LDSM4(bb[ni], btH + bRowB + ni * (16 * 80) + kB + bColB);
#pragma unroll
            for (int mi = 0; mi < 2; mi++)
#pragma unroll
                for (int ni = 0; ni < 4; ni++) {
                    MMA_BF16(acc[mi][2 * ni],     ah[mi], bb[ni][0], bb[ni][1]);
                    MMA_BF16(acc[mi][2 * ni + 1], ah[mi], bb[ni][2], bb[ni][3]);
                }
#pragma unroll
            for (int mi = 0; mi < 2; mi++)
                LDSM4(al[mi], atL + aRowB + mi * (16 * 80) + kB + aColB);
#pragma unroll
            for (int mi = 0; mi < 2; mi++)
#pragma unroll
                for (int ni = 0; ni < 4; ni++) {
                    MMA_BF16(acc[mi][2 * ni],     al[mi], bb[ni][0], bb[ni][1]);
                    MMA_BF16(acc[mi][2 * ni + 1], al[mi], bb[ni][2], bb[ni][3]);
                }
#pragma unroll
            for (int ni = 0; ni < 4; ni++)
                LDSM4(bb[ni], btL + bRowB + ni * (16 * 80) + kB + bColB);
#pragma unroll
            for (int mi = 0; mi < 2; mi++)
#pragma unroll
                for (int ni = 0; ni < 4; ni++) {
                    MMA_BF16(acc[mi][2 * ni],     ah[mi], bb[ni][0], bb[ni][1]);
                    MMA_BF16(acc[mi][2 * ni + 1], ah[mi], bb[ni][2], bb[ni][3]);
                }
        }
        __syncthreads();
        if (c + 2 < 32) load_stage(c + 2, (c + 2) % 3);
    }

    // Epilogue: stage fp32 in smem, then coalesced emit.
    float* Cs = (float*)smem;            // [128][132]
#pragma unroll
    for (int mi = 0; mi < 2; mi++)
#pragma unroll
        for (int nf = 0; nf < 8; nf++) {
            const int row0 = wm * 32 + mi * 16 + (lane >> 2);
            const int col  = wn * 64 + nf * 8 + (lane & 3) * 2;
            *(float2*)&Cs[row0 * 132 + col]       = make_float2(acc[mi][nf][0], acc[mi][nf][1]);
            *(float2*)&Cs[(row0 + 8) * 132 + col] = make_float2(acc[mi][nf][2], acc[mi][nf][3]);
        }
    __syncthreads();

#pragma unroll
    for (int it = 0; it < 16; it++) {
        const int lin = it * 256 + tid;
        const int rr = lin >> 5;
        const int cg = (lin & 31) * 4;
        float4 v = *(const float4*)&Cs[rr * 132 + cg];
        const int m = by * 128 + rr;
        const int n = bx * 128 + cg;
        if (MODE == 0) {
            const int b = m >> 11, s = m & 2047, h = n >> 6, d = n & 63;
            __nv_bfloat16* dh = (blockIdx.z == 0) ? g_Qhi : (blockIdx.z == 1 ? g_Khi : g_Vhi);
            __nv_bfloat16* dl = (blockIdx.z == 0) ? g_Qlo : (blockIdx.z == 1 ? g_Klo : g_Vlo);
            uint32_t u0 = packbf2(v.x, v.y), u1 = packbf2(v.z, v.w);
            uint32_t l0 = packbf2(v.x - bflo(u0), v.y - bfhi(u0));
            uint32_t l1 = packbf2(v.z - bflo(u1), v.w - bfhi(u1));
            size_t addr = (((size_t)(b * NH + h)) * SEQ + s) * DH + d;
            *(uint2*)&dh[addr] = make_uint2(u0, u1);
            *(uint2*)&dl[addr] = make_uint2(l0, l1);
        } else {
            *(float4*)&Cout[(size_t)m * EMB + n] = v;
        }
    }
}

// ---------------------------------------------------------------------------
// Flash attention on tensor cores.
// CTA = 128 q-rows of one (b,h). 8 warps, each owns 16 q-rows (m16 frags).
// QK^T: bf16x3; PV: bf16 P (l summed over rounded P) x hi/lo V.
// K/V double-buffered cp.async; Q resident in registers.
// ---------------------------------------------------------------------------
#define FL_SMEM (160*1024)
#define CEXP 0.18033688f     // 0.125 * log2(e)

__global__ __launch_bounds__(256, 1)
void flash_mma()
{
    const int qi = (int)gridDim.x - 1 - blockIdx.x;   // heavy tiles first
    const int h = blockIdx.y, b = blockIdx.z;
    const int tid = threadIdx.x, lane = tid & 31, w = tid >> 5;
    extern __shared__ __align__(128) char smf[];
    const uint32_t sb = smem_u32(smf);
    const uint32_t Qh_ = sb, Ql_ = sb + 16384;

    const size_t head = ((size_t)(b * NH + h)) * SEQ * DH;
    const __nv_bfloat16* Qhg = g_Qhi + head;
    const __nv_bfloat16* Qlg = g_Qlo + head;
    const __nv_bfloat16* Khg = g_Khi + head;
    const __nv_bfloat16* Klg = g_Klo + head;
    const __nv_bfloat16* Vhg = g_Vhi + head;
    const __nv_bfloat16* Vlg = g_Vlo + head;
    const int qbase = qi * 128;

    // Q tile loads (group 0)
#pragma unroll
    for (int i = 0; i < 4; i++) {
        int lin = i * 256 + tid;
        int r = lin >> 3, c = lin & 7;
        uint32_t off = swz(r * 128 + c * 16);
        CP_ASYNC16(Qh_ + off, Qhg + (size_t)(qbase + r) * 64 + c * 8);
        CP_ASYNC16(Ql_ + off, Qlg + (size_t)(qbase + r) * 64 + c * 8);
    }
    CP_COMMIT();

    auto load_kv = [&](int jt, int slot) {
        const uint32_t st = sb + 32768 + slot * 65536;
#pragma unroll
        for (int m = 0; m < 4; m++) {
            const __nv_bfloat16* g = (m == 0) ? Khg : (m == 1) ? Klg : (m == 2) ? Vhg : Vlg;
#pragma unroll
            for (int i = 0; i < 4; i++) {
                int lin = i * 256 + tid;
                int r = lin >> 3, c = lin & 7;
                CP_ASYNC16(st + m * 16384 + swz(r * 128 + c * 16),
                           g + (size_t)(jt * 128 + r) * 64 + c * 8);
            }
        }
        CP_COMMIT();
    };

    load_kv(0, 0);          // group 1
    CP_WAIT1();             // Q ready
    __syncthreads();

    // Q fragments (resident)
    uint32_t qh[4][4], ql[4][4];
    const uint32_t qoff = (w * 16 + (lane & 15)) * 128 + (lane >> 4) * 16;
#pragma unroll
    for (int kc = 0; kc < 4; kc++) {
        LDSM4(qh[kc], Qh_ + swz(qoff + kc * 32));
        LDSM4(ql[kc], Ql_ + swz(qoff + kc * 32));
    }

    float o_[8][4];
#pragma unroll
    for (int i = 0; i < 8; i++)
#pragma unroll
        for (int j = 0; j < 4; j++) o_[i][j] = 0.0f;
    float mrow[2] = {-3e38f, -3e38f};
    float lrow[2] = {0.0f, 0.0f};

    const int rA = qbase + w * 16 + (lane >> 2);
    const int rB = rA + 8;
    const uint32_t kOffBase = ((lane & 7) + ((lane >> 4) << 3)) * 128 + ((lane >> 3) & 1) * 16;
    const uint32_t vOffBase = (lane & 15) * 128 + (lane >> 4) * 16;

    for (int jt = 0; jt <= qi; jt++) {
        if (jt < qi) load_kv(jt + 1, (jt + 1) & 1);
        if (jt < qi) { CP_WAIT1(); } else { CP_WAIT0(); }
        __syncthreads();
        const uint32_t st = sb + 32768 + (jt & 1) * 65536;
        const uint32_t Kh_ = st, Kl_ = st + 16384, Vh_ = st + 32768, Vl_ = st + 49152;

        float s_[16][4];
#pragma unroll
        for (int i = 0; i < 16; i++)
#pragma unroll
            for (int j = 0; j < 4; j++) s_[i][j] = 0.0f;

        // ---- QK^T (bf16x3) ----
#pragma unroll
        for (int t = 0; t < 8; t++) {
#pragma unroll
            for (int kc = 0; kc < 4; kc++) {
                const uint32_t addr = swz(t * 16 * 128 + kOffBase + kc * 32);
                uint32_t bh[4], bl[4];
                LDSM4(bh, Kh_ + addr);
                LDSM4(bl, Kl_ + addr);
                MMA_BF16(s_[2 * t],     qh[kc], bh[0], bh[1]);
                MMA_BF16(s_[2 * t + 1], qh[kc], bh[2], bh[3]);
                MMA_BF16(s_[2 * t],     ql[kc], bh[0], bh[1]);
                MMA_BF16(s_[2 * t + 1], ql[kc], bh[2], bh[3]);
                MMA_BF16(s_[2 * t],     qh[kc], bl[0], bl[1]);
                MMA_BF16(s_[2 * t + 1], qh[kc], bl[2], bl[3]);
            }
        }

        // ---- causal mask (diagonal tile only) ----
        if (jt == qi) {
#pragma unroll
            for (int nf = 0; nf < 16; nf++) {
                const int colg = jt * 128 + nf * 8 + (lane & 3) * 2;
                if (colg     > rA) s_[nf][0] = -3e38f;
                if (colg + 1 > rA) s_[nf][1] = -3e38f;
                if (colg     > rB) s_[nf][2] = -3e38f;
                if (colg + 1 > rB) s_[nf][3] = -3e38f;
            }
        }

        // ---- online softmax ----
        float mx0 = -3e38f, mx1 = -3e38f;
#pragma unroll
        for (int nf = 0; nf < 16; nf++) {
            mx0 = fmaxf(mx0, fmaxf(s_[nf][0], s_[nf][1]));
            mx1 = fmaxf(mx1, fmaxf(s_[nf][2], s_[nf][3]));
        }
        mx0 = fmaxf(mx0, __shfl_xor_sync(0xffffffffu, mx0, 1));
        mx0 = fmaxf(mx0, __shfl_xor_sync(0xffffffffu, mx0, 2));
        mx1 = fmaxf(mx1, __shfl_xor_sync(0xffffffffu, mx1, 1));
        mx1 = fmaxf(mx1, __shfl_xor_sync(0xffffffffu, mx1, 2));
        const float mn0 = fmaxf(mrow[0], mx0);
        const float mn1 = fmaxf(mrow[1], mx1);
        const float c0 = exp2f((mrow[0] - mn0) * CEXP);
        const float c1 = exp2f((mrow[1] - mn1) * CEXP);
        mrow[0] = mn0; mrow[1] = mn1;

        uint32_t ph[8][4];
        float rs0 = 0.0f, rs1 = 0.0f;
#pragma unroll
        for (int j = 0; j < 8; j++) {
            const float p00 = exp2f((s_[2*j][0]   - mn0) * CEXP);
            const float p01 = exp2f((s_[2*j][1]   - mn0) * CEXP);
            const float p10 = exp2f((s_[2*j][2]   - mn1) * CEXP);
            const float p11 = exp2f((s_[2*j][3]   - mn1) * CEXP);
            const float p20 = exp2f((s_[2*j+1][0] - mn0) * CEXP);
            const float p21 = exp2f((s_[2*j+1][1] - mn0) * CEXP);
            const float p30 = exp2f((s_[2*j+1][2] - mn1) * CEXP);
            const float p31 = exp2f((s_[2*j+1][3] - mn1) * CEXP);
            ph[j][0] = packbf2(p00, p01);
            ph[j][1] = packbf2(p10, p11);
            ph[j][2] = packbf2(p20, p21);
            ph[j][3] = packbf2(p30, p31);
            // l accumulated from the ROUNDED p values actually used in PV
            rs0 += bflo(ph[j][0]) + bfhi(ph[j][0]) + bflo(ph[j][2]) + bfhi(ph[j][2]);
            rs1 += bflo(ph[j][1]) + bfhi(ph[j][1]) + bflo(ph[j][3]) + bfhi(ph[j][3]);
        }
        rs0 += __shfl_xor_sync(0xffffffffu, rs0, 1);
        rs0 += __shfl_xor_sync(0xffffffffu, rs0, 2);
        rs1 += __shfl_xor_sync(0xffffffffu, rs1, 1);
        rs1 += __shfl_xor_sync(0xffffffffu, rs1, 2);
        lrow[0] = lrow[0] * c0 + rs0;
        lrow[1] = lrow[1] * c1 + rs1;
#pragma unroll
        for (int nf = 0; nf < 8; nf++) {
            o_[nf][0] *= c0; o_[nf][1] *= c0;
            o_[nf][2] *= c1; o_[nf][3] *= c1;
        }

        // ---- PV (bf16 P x hi/lo V) ----
#pragma unroll
        for (int j = 0; j < 8; j++) {
#pragma unroll
            for (int t = 0; t < 4; t++) {
                const uint32_t addr = swz(j * 16 * 128 + vOffBase + t * 32);
                uint32_t vh[4], vl[4];
                LDSM4T(vh, Vh_ + addr);
                MMA_BF16(o_[2 * t],     ph[j], vh[0], vh[1]);
                MMA_BF16(o_[2 * t + 1], ph[j], vh[2], vh[3]);
                LDSM4T(vl, Vl_ + addr);
                MMA_BF16(o_[2 * t],     ph[j], vl[0], vl[1]);
                MMA_BF16(o_[2 * t + 1], ph[j], vl[2], vl[3]);
            }
        }
        __syncthreads();
    }

    // ---- epilogue: normalize, split hi/lo, write row-major for o-proj ----
    const float iA = 1.0f / lrow[0];
    const float iB = 1.0f / lrow[1];
    const size_t rowA = (size_t)(b * SEQ + rA) * EMB + h * 64;
    const size_t rowB = (size_t)(b * SEQ + rB) * EMB + h * 64;
#pragma unroll
    for (int nf = 0; nf < 8; nf++) {
        const int d = nf * 8 + (lane & 3) * 2;
        float x0 = o_[nf][0] * iA, x1 = o_[nf][1] * iA;
        uint32_t hp = packbf2(x0, x1);
        uint32_t lp = packbf2(x0 - bflo(hp), x1 - bfhi(hp));
        *(uint32_t*)&g_Ohi[rowA + d] = hp;
        *(uint32_t*)&g_Olo[rowA + d] = lp;
        float y0 = o_[nf][2] * iB, y1 = o_[nf][3] * iB;
        uint32_t hq = packbf2(y0, y1);
        uint32_t lq = packbf2(y0 - bflo(hq), y1 - bfhi(hq));
        *(uint32_t*)&g_Ohi[rowB + d] = hq;
        *(uint32_t*)&g_Olo[rowB + d] = lq;
    }
}

// ---------------------------------------------------------------------------
extern "C" void kernel_launch(void* const* d_in, const int* in_sizes, int n_in,
                              void* d_out, int out_size)
{
    const float* x  = (const float*)d_in[0];
    const float* Wq = (const float*)d_in[1];
    const float* Wk = (const float*)d_in[2];
    const float* Wv = (const float*)d_in[3];
    const float* Wo = (const float*)d_in[4];
    float* out = (float*)d_out;

    cudaFuncSetAttribute(gemm_mma<0>,
                         cudaFuncAttributeMaxDynamicSharedMemorySize, GEMM_SMEM);
    cudaFuncSetAttribute(gemm_mma<1>,
                         cudaFuncAttributeMaxDynamicSharedMemorySize, GEMM_SMEM);
    cudaFuncSetAttribute(flash_mma,
                         cudaFuncAttributeMaxDynamicSharedMemorySize, FL_SMEM);

    __nv_bfloat16 *xhi_p, *xlo_p, *ohi_p, *olo_p;
    cudaGetSymbolAddress((void**)&xhi_p, g_Xhi);
    cudaGetSymbolAddress((void**)&xlo_p, g_Xlo);
    cudaGetSymbolAddress((void**)&ohi_p, g_Ohi);
    cudaGetSymbolAddress((void**)&olo_p, g_Olo);

    convert_x_kernel<<<2048, 256>>>(x);
    convert_w_kernel<<<512, 256>>>(Wq, Wk, Wv, Wo);

    // QKV projections -> bf16 hi/lo head-major
    gemm_mma<0><<<dim3(8, 32, 3), 256, GEMM_SMEM>>>(xhi_p, xlo_p, nullptr);

    // Tensor-core causal flash attention -> Ohi/Olo row-major
    flash_mma<<<dim3(SEQ/128, NH, BATCH), 256, FL_SMEM>>>();

    // Output projection
    gemm_mma<1><<<dim3(8, 32, 1), 256, GEMM_SMEM>>>(ohi_p, olo_p, out);
}

// round 5
// speedup vs baseline: 3.1352x; 1.0919x over previous
#include <cuda_runtime.h>
#include <cuda_bf16.h>
#include <math.h>
#include <stdint.h>

#define BATCH 2
#define SEQ   2048
#define EMB   1024
#define NH    16
#define DH    64
#define M_TOT (BATCH*SEQ)   // 4096

// ---------------------------------------------------------------------------
// Device scratch (bf16 hi/lo everywhere)
// ---------------------------------------------------------------------------
__device__ __nv_bfloat16 g_Xhi[M_TOT*EMB];
__device__ __nv_bfloat16 g_Xlo[M_TOT*EMB];
__device__ __nv_bfloat16 g_Whi[4*EMB*EMB];
__device__ __nv_bfloat16 g_Wlo[4*EMB*EMB];
__device__ __nv_bfloat16 g_Qhi[BATCH*NH*SEQ*DH];
__device__ __nv_bfloat16 g_Qlo[BATCH*NH*SEQ*DH];
__device__ __nv_bfloat16 g_Khi[BATCH*NH*SEQ*DH];
__device__ __nv_bfloat16 g_Klo[BATCH*NH*SEQ*DH];
__device__ __nv_bfloat16 g_Vhi[BATCH*NH*SEQ*DH];
__device__ __nv_bfloat16 g_Vlo[BATCH*NH*SEQ*DH];
__device__ __nv_bfloat16 g_Ohi[M_TOT*EMB];
__device__ __nv_bfloat16 g_Olo[M_TOT*EMB];

// ---------------------------------------------------------------------------
// PTX helpers (portable sm_80-class only; target is bare sm_103)
// ---------------------------------------------------------------------------
__device__ __forceinline__ uint32_t smem_u32(const void* p) {
    uint32_t a;
    asm("{ .reg .u64 t; cvta.to.shared.u64 t, %1; cvt.u32.u64 %0, t; }" : "=r"(a) : "l"(p));
    return a;
}

#define CP_ASYNC16(dst, src) \
    asm volatile("cp.async.cg.shared.global [%0], [%1], 16;" :: "r"(dst), "l"(src))
#define CP_COMMIT() asm volatile("cp.async.commit_group;")
#define CP_WAIT0()  asm volatile("cp.async.wait_group 0;")
#define CP_WAIT1()  asm volatile("cp.async.wait_group 1;")

#define LDSM4(r, addr) \
    asm volatile("ldmatrix.sync.aligned.m8n8.x4.shared.b16 {%0,%1,%2,%3}, [%4];" \
        : "=r"((r)[0]), "=r"((r)[1]), "=r"((r)[2]), "=r"((r)[3]) : "r"(addr))
#define LDSM4T(r, addr) \
    asm volatile("ldmatrix.sync.aligned.m8n8.x4.trans.shared.b16 {%0,%1,%2,%3}, [%4];" \
        : "=r"((r)[0]), "=r"((r)[1]), "=r"((r)[2]), "=r"((r)[3]) : "r"(addr))

#define MMA_BF16(c, a, b0v, b1v) \
    asm volatile("mma.sync.aligned.m16n8k16.row.col.f32.bf16.bf16.f32 " \
        "{%0,%1,%2,%3}, {%4,%5,%6,%7}, {%8,%9}, {%0,%1,%2,%3};" \
        : "+f"((c)[0]), "+f"((c)[1]), "+f"((c)[2]), "+f"((c)[3]) \
        : "r"((a)[0]), "r"((a)[1]), "r"((a)[2]), "r"((a)[3]), "r"(b0v), "r"(b1v))

__device__ __forceinline__ uint32_t packbf2(float lo, float hi) {
    uint32_t r;
    asm("cvt.rn.bf16x2.f32 %0, %1, %2;" : "=r"(r) : "f"(hi), "f"(lo));
    return r;
}
__device__ __forceinline__ float bflo(uint32_t u) { return __uint_as_float(u << 16); }
__device__ __forceinline__ float bfhi(uint32_t u) { return __uint_as_float(u & 0xFFFF0000u); }

__device__ __forceinline__ uint32_t swz(uint32_t off) {   // SW128 for 128B rows
    return off ^ ((off >> 3) & 0x70);
}

// ---------------------------------------------------------------------------
// Conversion kernels: fp32 -> bf16 hi/lo (row-major)
// ---------------------------------------------------------------------------
__device__ __forceinline__ void split8_store(const float* vs, __nv_bfloat16* hi,
                                             __nv_bfloat16* lo, size_t base) {
    __nv_bfloat16 h[8], l[8];
#pragma unroll
    for (int i = 0; i < 8; i++) {
        h[i] = __float2bfloat16(vs[i]);
        l[i] = __float2bfloat16(vs[i] - __bfloat162float(h[i]));
    }
    *(uint4*)&hi[base] = *(uint4*)h;
    *(uint4*)&lo[base] = *(uint4*)l;
}

__global__ void convert_x_kernel(const float* __restrict__ X) {
    int gid = blockIdx.x * 256 + threadIdx.x;
    size_t base = (size_t)gid * 8;
    float4 v0 = *(const float4*)&X[base];
    float4 v1 = *(const float4*)&X[base + 4];
    float vs[8] = {v0.x, v0.y, v0.z, v0.w, v1.x, v1.y, v1.z, v1.w};
    split8_store(vs, g_Xhi, g_Xlo, base);
}

// Transpose W[K][N] -> Wt[N][K] while converting to hi/lo.
__global__ void convert_w_kernel(const float* __restrict__ W0, const float* __restrict__ W1,
                                 const float* __restrict__ W2, const float* __restrict__ W3) {
    __shared__ float Wsm[64][129];
    int bi = blockIdx.x;                 // 0..511
    int w = bi >> 7;
    int rest = bi & 127;
    int ntile = rest >> 4;
    int kc = rest & 15;
    const float* W = (w == 0) ? W0 : (w == 1) ? W1 : (w == 2) ? W2 : W3;
    int tid = threadIdx.x;

#pragma unroll
    for (int i = 0; i < 32; i++) {
        int lin = i * 256 + tid;
        int kr = lin >> 7;
        int nc = lin & 127;
        Wsm[kr][nc] = W[(size_t)(kc * 64 + kr) * EMB + ntile * 128 + nc];
    }
    __syncthreads();

#pragma unroll
    for (int j = 0; j < 4; j++) {
        int lin = j * 256 + tid;
        int nin = lin >> 3;
        int g = lin & 7;
        float vs[8];
#pragma unroll
        for (int i = 0; i < 8; i++) vs[i] = Wsm[g * 8 + i][nin];
        size_t base = ((size_t)(w * EMB + ntile * 128 + nin)) * EMB + kc * 64 + g * 8;
        split8_store(vs, g_Whi, g_Wlo, base);
    }
}

// ---------------------------------------------------------------------------
// mma.sync bf16x3 GEMM (CTA 256x128, warp tile 64x64, BK=32, 3-stage).
// MODE 0: A=X, B=W[z]; epilogue -> bf16 hi/lo head-major Q/K/V.
// MODE 1: A=Ohi/Olo,  B=W[3];  epilogue -> fp32 row-major Cout.
// ---------------------------------------------------------------------------
#define A_TILE_B 20480                   // 256 rows * 80B
#define B_TILE_B 10240                   // 128 rows * 80B
#define STAGE_BYTES (2*A_TILE_B + 2*B_TILE_B)   // 61440
#define GEMM_SMEM (3*STAGE_BYTES)        // 184320

template<int MODE>
__global__ __launch_bounds__(256)
void gemm_mma(const __nv_bfloat16* __restrict__ Ahi,
              const __nv_bfloat16* __restrict__ Alo,
              float* __restrict__ Cout)
{
    extern __shared__ __align__(128) char smem[];
    const uint32_t sb = smem_u32(smem);
    const int tid = threadIdx.x, lane = tid & 31, wid = tid >> 5;
    const int wm = wid & 3, wn = wid >> 2;
    const int bx = blockIdx.x, by = blockIdx.y;
    const int w = (MODE == 0) ? blockIdx.z : 3;

    const __nv_bfloat16* Bhi = g_Whi + (size_t)w * EMB * EMB;
    const __nv_bfloat16* Blo = g_Wlo + (size_t)w * EMB * EMB;

    float acc[4][8][4];
#pragma unroll
    for (int i = 0; i < 4; i++)
#pragma unroll
        for (int j = 0; j < 8; j++)
#pragma unroll
            for (int q = 0; q < 4; q++) acc[i][j][q] = 0.0f;

    const int lr = tid >> 2;             // 0..63
    const int ls4 = tid & 3;             // 16B segment

    auto load_stage = [&](int c, int slot) {
        const int k0 = c * 32;
        const uint32_t st = sb + slot * STAGE_BYTES;
        // A hi/lo: 256 rows each, 4 per-thread rows
#pragma unroll
        for (int i = 0; i < 4; i++) {
            const int r = i * 64 + lr;
            CP_ASYNC16(st + r * 80 + ls4 * 16,
                       Ahi + (size_t)(by * 256 + r) * EMB + k0 + ls4 * 8);
            CP_ASYNC16(st + A_TILE_B + r * 80 + ls4 * 16,
                       Alo + (size_t)(by * 256 + r) * EMB + k0 + ls4 * 8);
        }
        // B hi/lo: 128 rows each, 2 per-thread rows
#pragma unroll
        for (int i = 0; i < 2; i++) {
            const int r = i * 64 + lr;
            CP_ASYNC16(st + 2 * A_TILE_B + r * 80 + ls4 * 16,
                       Bhi + (size_t)(bx * 128 + r) * EMB + k0 + ls4 * 8);
            CP_ASYNC16(st + 2 * A_TILE_B + B_TILE_B + r * 80 + ls4 * 16,
                       Blo + (size_t)(bx * 128 + r) * EMB + k0 + ls4 * 8);
        }
        CP_COMMIT();
    };

    load_stage(0, 0);
    load_stage(1, 1);

    const uint32_t aRowB  = (wm * 64 + (lane & 15)) * 80;
    const uint32_t aColB  = (lane >> 4) * 16;
    const uint32_t bRowB  = (wn * 64 + (lane & 7) + ((lane >> 4) << 3)) * 80;
    const uint32_t bColB  = ((lane >> 3) & 1) * 16;

    for (int c = 0; c < 32; c++) {
        CP_WAIT1();
        __syncthreads();
        const uint32_t st = sb + (c % 3) * STAGE_BYTES;
        const uint32_t atH = st, atL = st + A_TILE_B;
        const uint32_t btH = st + 2 * A_TILE_B, btL = st + 2 * A_TILE_B + B_TILE_B;

#pragma unroll
        for (int kc = 0; kc < 2; kc++) {
            const uint32_t kB = kc * 32;
            uint32_t ah[4][4], al[4][4], bb[4][4];
#pragma unroll
            for (int mi = 0; mi < 4; mi++)
                LDSM4(ah[mi], atH + aRowB + mi * (16 * 80) + kB + aColB);
#pragma unroll
            for (int ni = 0; ni < 4; ni++)
                LDSM4(bb[ni], btH + bRowB + ni * (16 * 80) + kB + bColB);
#pragma unroll
            for (int mi = 0; mi < 4; mi++)
#pragma unroll
                for (int ni = 0; ni < 4; ni++) {
                    MMA_BF16(acc[mi][2 * ni],     ah[mi], bb[ni][0], bb[ni][1]);
                    MMA_BF16(acc[mi][2 * ni + 1], ah[mi], bb[ni][2], bb[ni][3]);
                }
#pragma unroll
            for (int mi = 0; mi < 4; mi++)
                LDSM4(al[mi], atL + aRowB + mi * (16 * 80) + kB + aColB);
#pragma unroll
            for (int mi = 0; mi < 4; mi++)
#pragma unroll
                for (int ni = 0; ni < 4; ni++) {
                    MMA_BF16(acc[mi][2 * ni],     al[mi], bb[ni][0], bb[ni][1]);
                    MMA_BF16(acc[mi][2 * ni + 1], al[mi], bb[ni][2], bb[ni][3]);
                }
#pragma unroll
            for (int ni = 0; ni < 4; ni++)
                LDSM4(bb[ni], btL + bRowB + ni * (16 * 80) + kB + bColB);
#pragma unroll
            for (int mi = 0; mi < 4; mi++)
#pragma unroll
                for (int ni = 0; ni < 4; ni++) {
                    MMA_BF16(acc[mi][2 * ni],     ah[mi], bb[ni][0], bb[ni][1]);
                    MMA_BF16(acc[mi][2 * ni + 1], ah[mi], bb[ni][2], bb[ni][3]);
                }
        }
        __syncthreads();
        if (c + 2 < 32) load_stage(c + 2, (c + 2) % 3);
    }

    // Epilogue: stage fp32 in smem, then coalesced emit.
    float* Cs = (float*)smem;            // [256][132] = 135168B
#pragma unroll
    for (int mi = 0; mi < 4; mi++)
#pragma unroll
        for (int nf = 0; nf < 8; nf++) {
            const int row0 = wm * 64 + mi * 16 + (lane >> 2);
            const int col  = wn * 64 + nf * 8 + (lane & 3) * 2;
            *(float2*)&Cs[row0 * 132 + col]       = make_float2(acc[mi][nf][0], acc[mi][nf][1]);
            *(float2*)&Cs[(row0 + 8) * 132 + col] = make_float2(acc[mi][nf][2], acc[mi][nf][3]);
        }
    __syncthreads();

#pragma unroll
    for (int it = 0; it < 32; it++) {
        const int lin = it * 256 + tid;  // 8192 float4 slots
        const int rr = lin >> 5;
        const int cg = (lin & 31) * 4;
        float4 v = *(const float4*)&Cs[rr * 132 + cg];
        const int m = by * 256 + rr;
        const int n = bx * 128 + cg;
        if (MODE == 0) {
            const int b = m >> 11, s = m & 2047, h = n >> 6, d = n & 63;
            __nv_bfloat16* dh = (blockIdx.z == 0) ? g_Qhi : (blockIdx.z == 1 ? g_Khi : g_Vhi);
            __nv_bfloat16* dl = (blockIdx.z == 0) ? g_Qlo : (blockIdx.z == 1 ? g_Klo : g_Vlo);
            uint32_t u0 = packbf2(v.x, v.y), u1 = packbf2(v.z, v.w);
            uint32_t l0 = packbf2(v.x - bflo(u0), v.y - bfhi(u0));
            uint32_t l1 = packbf2(v.z - bflo(u1), v.w - bfhi(u1));
            size_t addr = (((size_t)(b * NH + h)) * SEQ + s) * DH + d;
            *(uint2*)&dh[addr] = make_uint2(u0, u1);
            *(uint2*)&dl[addr] = make_uint2(l0, l1);
        } else {
            *(float4*)&Cout[(size_t)m * EMB + n] = v;
        }
    }
}

// ---------------------------------------------------------------------------
// Flash attention on tensor cores (unchanged from round 4 — known good).
// ---------------------------------------------------------------------------
#define FL_SMEM (160*1024)
#define CEXP 0.18033688f     // 0.125 * log2(e)

__global__ __launch_bounds__(256, 1)
void flash_mma()
{
    const int qi = (int)gridDim.x - 1 - blockIdx.x;   // heavy tiles first
    const int h = blockIdx.y, b = blockIdx.z;
    const int tid = threadIdx.x, lane = tid & 31, w = tid >> 5;
    extern __shared__ __align__(128) char smf[];
    const uint32_t sb = smem_u32(smf);
    const uint32_t Qh_ = sb, Ql_ = sb + 16384;

    const size_t head = ((size_t)(b * NH + h)) * SEQ * DH;
    const __nv_bfloat16* Qhg = g_Qhi + head;
    const __nv_bfloat16* Qlg = g_Qlo + head;
    const __nv_bfloat16* Khg = g_Khi + head;
    const __nv_bfloat16* Klg = g_Klo + head;
    const __nv_bfloat16* Vhg = g_Vhi + head;
    const __nv_bfloat16* Vlg = g_Vlo + head;
    const int qbase = qi * 128;

#pragma unroll
    for (int i = 0; i < 4; i++) {
        int lin = i * 256 + tid;
        int r = lin >> 3, c = lin & 7;
        uint32_t off = swz(r * 128 + c * 16);
        CP_ASYNC16(Qh_ + off, Qhg + (size_t)(qbase + r) * 64 + c * 8);
        CP_ASYNC16(Ql_ + off, Qlg + (size_t)(qbase + r) * 64 + c * 8);
    }
    CP_COMMIT();

    auto load_kv = [&](int jt, int slot) {
        const uint32_t st = sb + 32768 + slot * 65536;
#pragma unroll
        for (int m = 0; m < 4; m++) {
            const __nv_bfloat16* g = (m == 0) ? Khg : (m == 1) ? Klg : (m == 2) ? Vhg : Vlg;
#pragma unroll
            for (int i = 0; i < 4; i++) {
                int lin = i * 256 + tid;
                int r = lin >> 3, c = lin & 7;
                CP_ASYNC16(st + m * 16384 + swz(r * 128 + c * 16),
                           g + (size_t)(jt * 128 + r) * 64 + c * 8);
            }
        }
        CP_COMMIT();
    };

    load_kv(0, 0);
    CP_WAIT1();
    __syncthreads();

    uint32_t qh[4][4], ql[4][4];
    const uint32_t qoff = (w * 16 + (lane & 15)) * 128 + (lane >> 4) * 16;
#pragma unroll
    for (int kc = 0; kc < 4; kc++) {
        LDSM4(qh[kc], Qh_ + swz(qoff + kc * 32));
        LDSM4(ql[kc], Ql_ + swz(qoff + kc * 32));
    }

    float o_[8][4];
#pragma unroll
    for (int i = 0; i < 8; i++)
#pragma unroll
        for (int j = 0; j < 4; j++) o_[i][j] = 0.0f;
    float mrow[2] = {-3e38f, -3e38f};
    float lrow[2] = {0.0f, 0.0f};

    const int rA = qbase + w * 16 + (lane >> 2);
    const int rB = rA + 8;
    const uint32_t kOffBase = ((lane & 7) + ((lane >> 4) << 3)) * 128 + ((lane >> 3) & 1) * 16;
    const uint32_t vOffBase = (lane & 15) * 128 + (lane >> 4) * 16;

    for (int jt = 0; jt <= qi; jt++) {
        if (jt < qi) load_kv(jt + 1, (jt + 1) & 1);
        if (jt < qi) { CP_WAIT1(); } else { CP_WAIT0(); }
        __syncthreads();
        const uint32_t st = sb + 32768 + (jt & 1) * 65536;
        const uint32_t Kh_ = st, Kl_ = st + 16384, Vh_ = st + 32768, Vl_ = st + 49152;

        float s_[16][4];
#pragma unroll
        for (int i = 0; i < 16; i++)
#pragma unroll
            for (int j = 0; j < 4; j++) s_[i][j] = 0.0f;

#pragma unroll
        for (int t = 0; t < 8; t++) {
#pragma unroll
            for (int kc = 0; kc < 4; kc++) {
                const uint32_t addr = swz(t * 16 * 128 + kOffBase + kc * 32);
                uint32_t bh[4], bl[4];
                LDSM4(bh, Kh_ + addr);
                LDSM4(bl, Kl_ + addr);
                MMA_BF16(s_[2 * t],     qh[kc], bh[0], bh[1]);
                MMA_BF16(s_[2 * t + 1], qh[kc], bh[2], bh[3]);
                MMA_BF16(s_[2 * t],     ql[kc], bh[0], bh[1]);
                MMA_BF16(s_[2 * t + 1], ql[kc], bh[2], bh[3]);
                MMA_BF16(s_[2 * t],     qh[kc], bl[0], bl[1]);
                MMA_BF16(s_[2 * t + 1], qh[kc], bl[2], bl[3]);
            }
        }

        if (jt == qi) {
#pragma unroll
            for (int nf = 0; nf < 16; nf++) {
                const int colg = jt * 128 + nf * 8 + (lane & 3) * 2;
                if (colg     > rA) s_[nf][0] = -3e38f;
                if (colg + 1 > rA) s_[nf][1] = -3e38f;
                if (colg     > rB) s_[nf][2] = -3e38f;
                if (colg + 1 > rB) s_[nf][3] = -3e38f;
            }
        }

        float mx0 = -3e38f, mx1 = -3e38f;
#pragma unroll
        for (int nf = 0; nf < 16; nf++) {
            mx0 = fmaxf(mx0, fmaxf(s_[nf][0], s_[nf][1]));
            mx1 = fmaxf(mx1, fmaxf(s_[nf][2], s_[nf][3]));
        }
        mx0 = fmaxf(mx0, __shfl_xor_sync(0xffffffffu, mx0, 1));
        mx0 = fmaxf(mx0, __shfl_xor_sync(0xffffffffu, mx0, 2));
        mx1 = fmaxf(mx1, __shfl_xor_sync(0xffffffffu, mx1, 1));
        mx1 = fmaxf(mx1, __shfl_xor_sync(0xffffffffu, mx1, 2));
        const float mn0 = fmaxf(mrow[0], mx0);
        const float mn1 = fmaxf(mrow[1], mx1);
        const float c0 = exp2f((mrow[0] - mn0) * CEXP);
        const float c1 = exp2f((mrow[1] - mn1) * CEXP);
        mrow[0] = mn0; mrow[1] = mn1;

        uint32_t ph[8][4];
        float rs0 = 0.0f, rs1 = 0.0f;
#pragma unroll
        for (int j = 0; j < 8; j++) {
            const float p00 = exp2f((s_[2*j][0]   - mn0) * CEXP);
            const float p01 = exp2f((s_[2*j][1]   - mn0) * CEXP);
            const float p10 = exp2f((s_[2*j][2]   - mn1) * CEXP);
            const float p11 = exp2f((s_[2*j][3]   - mn1) * CEXP);
            const float p20 = exp2f((s_[2*j+1][0] - mn0) * CEXP);
            const float p21 = exp2f((s_[2*j+1][1] - mn0) * CEXP);
            const float p30 = exp2f((s_[2*j+1][2] - mn1) * CEXP);
            const float p31 = exp2f((s_[2*j+1][3] - mn1) * CEXP);
            ph[j][0] = packbf2(p00, p01);
            ph[j][1] = packbf2(p10, p11);
            ph[j][2] = packbf2(p20, p21);
            ph[j][3] = packbf2(p30, p31);
            rs0 += bflo(ph[j][0]) + bfhi(ph[j][0]) + bflo(ph[j][2]) + bfhi(ph[j][2]);
            rs1 += bflo(ph[j][1]) + bfhi(ph[j][1]) + bflo(ph[j][3]) + bfhi(ph[j][3]);
        }
        rs0 += __shfl_xor_sync(0xffffffffu, rs0, 1);
        rs0 += __shfl_xor_sync(0xffffffffu, rs0, 2);
        rs1 += __shfl_xor_sync(0xffffffffu, rs1, 1);
        rs1 += __shfl_xor_sync(0xffffffffu, rs1, 2);
        lrow[0] = lrow[0] * c0 + rs0;
        lrow[1] = lrow[1] * c1 + rs1;
#pragma unroll
        for (int nf = 0; nf < 8; nf++) {
            o_[nf][0] *= c0; o_[nf][1] *= c0;
            o_[nf][2] *= c1; o_[nf][3] *= c1;
        }

#pragma unroll
        for (int j = 0; j < 8; j++) {
#pragma unroll
            for (int t = 0; t < 4; t++) {
                const uint32_t addr = swz(j * 16 * 128 + vOffBase + t * 32);
                uint32_t vh[4], vl[4];
                LDSM4T(vh, Vh_ + addr);
                MMA_BF16(o_[2 * t],     ph[j], vh[0], vh[1]);
                MMA_BF16(o_[2 * t + 1], ph[j], vh[2], vh[3]);
                LDSM4T(vl, Vl_ + addr);
                MMA_BF16(o_[2 * t],     ph[j], vl[0], vl[1]);
                MMA_BF16(o_[2 * t + 1], ph[j], vl[2], vl[3]);
            }
        }
        __syncthreads();
    }

    const float iA = 1.0f / lrow[0];
    const float iB = 1.0f / lrow[1];
    const size_t rowA = (size_t)(b * SEQ + rA) * EMB + h * 64;
    const size_t rowB = (size_t)(b * SEQ + rB) * EMB + h * 64;
#pragma unroll
    for (int nf = 0; nf < 8; nf++) {
        const int d = nf * 8 + (lane & 3) * 2;
        float x0 = o_[nf][0] * iA, x1 = o_[nf][1] * iA;
        uint32_t hp = packbf2(x0, x1);
        uint32_t lp = packbf2(x0 - bflo(hp), x1 - bfhi(hp));
        *(uint32_t*)&g_Ohi[rowA + d] = hp;
        *(uint32_t*)&g_Olo[rowA + d] = lp;
        float y0 = o_[nf][2] * iB, y1 = o_[nf][3] * iB;
        uint32_t hq = packbf2(y0, y1);
        uint32_t lq = packbf2(y0 - bflo(hq), y1 - bfhi(hq));
        *(uint32_t*)&g_Ohi[rowB + d] = hq;
        *(uint32_t*)&g_Olo[rowB + d] = lq;
    }
}

// ---------------------------------------------------------------------------
extern "C" void kernel_launch(void* const* d_in, const int* in_sizes, int n_in,
                              void* d_out, int out_size)
{
    const float* x  = (const float*)d_in[0];
    const float* Wq = (const float*)d_in[1];
    const float* Wk = (const float*)d_in[2];
    const float* Wv = (const float*)d_in[3];
    const float* Wo = (const float*)d_in[4];
    float* out = (float*)d_out;

    cudaFuncSetAttribute(gemm_mma<0>,
                         cudaFuncAttributeMaxDynamicSharedMemorySize, GEMM_SMEM);
    cudaFuncSetAttribute(gemm_mma<1>,
                         cudaFuncAttributeMaxDynamicSharedMemorySize, GEMM_SMEM);
    cudaFuncSetAttribute(flash_mma,
                         cudaFuncAttributeMaxDynamicSharedMemorySize, FL_SMEM);

    __nv_bfloat16 *xhi_p, *xlo_p, *ohi_p, *olo_p;
    cudaGetSymbolAddress((void**)&xhi_p, g_Xhi);
    cudaGetSymbolAddress((void**)&xlo_p, g_Xlo);
    cudaGetSymbolAddress((void**)&ohi_p, g_Ohi);
    cudaGetSymbolAddress((void**)&olo_p, g_Olo);

    convert_x_kernel<<<2048, 256>>>(x);
    convert_w_kernel<<<512, 256>>>(Wq, Wk, Wv, Wo);

    // QKV projections -> bf16 hi/lo head-major (256x128 tiles)
    gemm_mma<0><<<dim3(8, 16, 3), 256, GEMM_SMEM>>>(xhi_p, xlo_p, nullptr);

    // Tensor-core causal flash attention -> Ohi/Olo row-major
    flash_mma<<<dim3(SEQ/128, NH, BATCH), 256, FL_SMEM>>>();

    // Output projection
    gemm_mma<1><<<dim3(8, 16, 1), 256, GEMM_SMEM>>>(ohi_p, olo_p, out);
}